// round 6
// baseline (speedup 1.0000x reference)
#include <cuda_runtime.h>
#include <cuda_bf16.h>
#include <math.h>
#include <cstdint>

// Problem dims
constexpr int BB = 64;    // batch
constexpr int TT = 256;   // time steps
constexpr int II = 256;   // input dim
constexpr int HH = 1024;  // hidden
constexpr int CC = 60;    // classes
constexpr int GG = 4096;  // 4*H
constexpr int NCTA = 128; // persistent CTAs; each owns 8 h-cols x 4 gates = 32 gate cols

// Dynamic SMEM layout (lstm_kernel): two k-half groups, k64 chunks
constexpr int A_HI = 0;        // [kh:2][buf:2][8KB]  (64 rows x 64 bf16, SW128)
constexpr int A_LO = 32768;    // same shape
constexpr int WF_HI = 65536;   // 64KB fragment-direct W hi
constexpr int WF_LO = 131072;  // 64KB fragment-direct W lo
constexpr int SG0 = 196608;    // 2 x 9216B gate-exchange (kh=0, kh=1 partials)
constexpr int SMEM_DYN = 215040;

// Dynamic SMEM layout (xproj_mma kernel)
constexpr int XA_HI = 0;       // 2 bufs x 16KB (128 rows x 64 bf16, SW128)
constexpr int XA_LO = 32768;   // 2 bufs x 16KB
constexpr int XW_HI = 65536;   // 32KB fragment-direct W_ih hi (64 cols x 256 k)
constexpr int XW_LO = 98304;   // 32KB
constexpr int SMEM_X = 131072;

// Scratch (__device__ globals: allocation-free)
__device__ float g_xproj[(size_t)TT * BB * GG];   // [t][b][g]
__device__ __nv_bfloat16 g_hhi[2][BB * HH];       // h hi, ping-pong
__device__ __nv_bfloat16 g_hlo[2][BB * HH];       // h lo, ping-pong
__device__ __nv_bfloat16 g_xhi[BB * TT * II];     // inputs hi  [(b*T+t)][i]
__device__ __nv_bfloat16 g_xlo[BB * TT * II];
__device__ __nv_bfloat16 g_wihhi[GG * II];        // W_ih hi [g][i]
__device__ __nv_bfloat16 g_wihlo[GG * II];
__device__ unsigned g_cnt[8];                     // per-column-group step counters

// ---------------------------------------------------------------------------
// helpers
// ---------------------------------------------------------------------------
__device__ __forceinline__ uint32_t smem_u32(const void* p) {
    uint32_t a;
    asm("{ .reg .u64 t; cvta.to.shared.u64 t, %1; cvt.u32.u64 %0, t; }" : "=r"(a) : "l"(p));
    return a;
}
__device__ __forceinline__ void ldm_x4(uint32_t* r, uint32_t addr) {
    asm volatile("ldmatrix.sync.aligned.m8n8.x4.shared.b16 {%0,%1,%2,%3}, [%4];"
                 : "=r"(r[0]), "=r"(r[1]), "=r"(r[2]), "=r"(r[3]) : "r"(addr));
}
__device__ __forceinline__ void mma_bf16(float* d, const uint32_t* a, uint32_t b0, uint32_t b1) {
    asm volatile(
        "mma.sync.aligned.m16n8k16.row.col.f32.bf16.bf16.f32 "
        "{%0,%1,%2,%3}, {%4,%5,%6,%7}, {%8,%9}, {%0,%1,%2,%3};"
        : "+f"(d[0]), "+f"(d[1]), "+f"(d[2]), "+f"(d[3])
        : "r"(a[0]), "r"(a[1]), "r"(a[2]), "r"(a[3]), "r"(b0), "r"(b1));
}
__device__ __forceinline__ void cp16(uint32_t smem, const void* g) {
    asm volatile("cp.async.cg.shared.global [%0], [%1], 16;" :: "r"(smem), "l"(g));
}
#define CP_COMMIT() asm volatile("cp.async.commit_group;" ::: "memory")
#define CP_WAIT(n)  asm volatile("cp.async.wait_group %0;" :: "n"(n) : "memory")
#define GBAR(id)    asm volatile("bar.sync %0, 256;" :: "r"(id) : "memory")

__device__ __forceinline__ uint32_t pack2(__nv_bfloat16 a, __nv_bfloat16 b) {
    return (uint32_t)*(uint16_t*)&a | ((uint32_t)*(uint16_t*)&b << 16);
}
__device__ __forceinline__ float2 unpack2(uint32_t v) {
    __nv_bfloat16 a, b;
    uint16_t x = (uint16_t)v, y = (uint16_t)(v >> 16);
    a = *(__nv_bfloat16*)&x; b = *(__nv_bfloat16*)&y;
    return make_float2(__bfloat162float(a), __bfloat162float(b));
}
__device__ __forceinline__ void poll_ge(const unsigned* p, unsigned tgt) {
    unsigned v;
    do {
        asm volatile("ld.acquire.gpu.global.u32 %0, [%1];" : "=r"(v) : "l"(p) : "memory");
    } while (v < tgt);
}
__device__ __forceinline__ float fsigmoid(float x) {
    return __fdividef(1.f, 1.f + __expf(-x));
}
__device__ __forceinline__ float ftanh(float x) {
    return 1.f - __fdividef(2.f, __expf(2.f * x) + 1.f);
}

// ---------------------------------------------------------------------------
// Zero-init h buffers + group counters.
// ---------------------------------------------------------------------------
__global__ void zero_kernel() {
    int i = blockIdx.x * blockDim.x + threadIdx.x;
    if (i < BB * HH) {
        ((unsigned*)g_hhi)[i] = 0u;
        ((unsigned*)g_hlo)[i] = 0u;
    }
    if (i < 8) g_cnt[i] = 0u;
}

// ---------------------------------------------------------------------------
// Convert inputs and W_ih to bf16 hi/lo split (row-major, same layout).
// ---------------------------------------------------------------------------
__global__ void conv_kernel(const float* __restrict__ inp, const float* __restrict__ Wih) {
    int stride = gridDim.x * blockDim.x;
    int i0 = blockIdx.x * blockDim.x + threadIdx.x;
    for (int i = i0; i < 1048576; i += stride) {
        float4 v = ((const float4*)inp)[i];
        __nv_bfloat16 hx = __float2bfloat16(v.x), hy = __float2bfloat16(v.y);
        __nv_bfloat16 hz = __float2bfloat16(v.z), hw = __float2bfloat16(v.w);
        uint2 hi = make_uint2(pack2(hx, hy), pack2(hz, hw));
        uint2 lo = make_uint2(
            pack2(__float2bfloat16(v.x - __bfloat162float(hx)), __float2bfloat16(v.y - __bfloat162float(hy))),
            pack2(__float2bfloat16(v.z - __bfloat162float(hz)), __float2bfloat16(v.w - __bfloat162float(hw))));
        ((uint2*)g_xhi)[i] = hi;
        ((uint2*)g_xlo)[i] = lo;
    }
    for (int i = i0; i < 262144; i += stride) {
        float4 v = ((const float4*)Wih)[i];
        __nv_bfloat16 hx = __float2bfloat16(v.x), hy = __float2bfloat16(v.y);
        __nv_bfloat16 hz = __float2bfloat16(v.z), hw = __float2bfloat16(v.w);
        uint2 hi = make_uint2(pack2(hx, hy), pack2(hz, hw));
        uint2 lo = make_uint2(
            pack2(__float2bfloat16(v.x - __bfloat162float(hx)), __float2bfloat16(v.y - __bfloat162float(hy))),
            pack2(__float2bfloat16(v.z - __bfloat162float(hz)), __float2bfloat16(v.w - __bfloat162float(hw))));
        ((uint2*)g_wihhi)[i] = hi;
        ((uint2*)g_wihlo)[i] = lo;
    }
}

// ---------------------------------------------------------------------------
// x_proj via split-bf16 mma.sync (proven round 4).
// ---------------------------------------------------------------------------
__global__ __launch_bounds__(256, 1) void xproj_mma_kernel(
    const float* __restrict__ bih, const float* __restrict__ bhh) {
    extern __shared__ char sm[];
    const int tid = threadIdx.x;
    const int lane = tid & 31;
    const int w = tid >> 5;
    const int n0 = blockIdx.x * 64;
    const uint32_t smb = smem_u32(sm);

    for (int idx = tid; idx < 8192; idx += 256) {
        int q = idx & 15, ln = (idx >> 4) & 31, ks = idx >> 9;
        int nt = q >> 1, rr = q & 1;
        int nl = nt * 8 + (ln >> 2);
        int k = ks * 16 + rr * 8 + (ln & 3) * 2;
        uint32_t vh = *(const uint32_t*)(g_wihhi + (n0 + nl) * II + k);
        uint32_t vl = *(const uint32_t*)(g_wihlo + (n0 + nl) * II + k);
        ((uint32_t*)(sm + XW_HI))[idx] = vh;
        ((uint32_t*)(sm + XW_LO))[idx] = vl;
    }
    __syncthreads();

    const int grp = lane >> 2, tg = lane & 3;
    float bias0[8], bias1[8];
#pragma unroll
    for (int nt = 0; nt < 8; nt++) {
        int g = n0 + nt * 8 + tg * 2;
        bias0[nt] = bih[g] + bhh[g];
        bias1[nt] = bih[g + 1] + bhh[g + 1];
    }

    const int arow = w * 16 + (lane & 15);
    const int acol = (lane >> 4) * 16;

    for (int miter = 0; miter < 8; miter++) {
        const int m0 = (blockIdx.y * 8 + miter) * 128;

        float acc[8][4];
#pragma unroll
        for (int z = 0; z < 8; z++)
#pragma unroll
            for (int r = 0; r < 4; r++) acc[z][r] = 0.f;

#pragma unroll
        for (int i = 0; i < 4; i++) {
            int s = i * 256 + tid;
            int row = s >> 3, sb = s & 7;
            int gidx = (m0 + row) * 32 + sb;
            uint4 vh = ((const uint4*)g_xhi)[gidx];
            uint4 vl = ((const uint4*)g_xlo)[gidx];
            int off = row * 128 + sb * 16;
            int sw = off ^ ((off >> 3) & 0x70);
            *(uint4*)(sm + XA_HI + sw) = vh;
            *(uint4*)(sm + XA_LO + sw) = vl;
        }
        __syncthreads();

        for (int ch = 0; ch < 4; ch++) {
            const int buf = ch & 1;
            uint4 ph[4], pl[4];
            if (ch < 3) {
#pragma unroll
                for (int i = 0; i < 4; i++) {
                    int s = i * 256 + tid;
                    int row = s >> 3, sb = s & 7;
                    int gidx = (m0 + row) * 32 + (ch + 1) * 8 + sb;
                    ph[i] = ((const uint4*)g_xhi)[gidx];
                    pl[i] = ((const uint4*)g_xlo)[gidx];
                }
            }
            const uint32_t abh = smb + XA_HI + buf * 16384;
            const uint32_t abl = smb + XA_LO + buf * 16384;
#pragma unroll
            for (int kl = 0; kl < 4; kl++) {
                const int ks = ch * 4 + kl;
                int off = arow * 128 + kl * 32 + acol;
                int sw = off ^ ((off >> 3) & 0x70);
                uint32_t ah[4], al[4];
                ldm_x4(ah, abh + sw);
                ldm_x4(al, abl + sw);
                const uint4* wh4 = (const uint4*)(sm + XW_HI) + (ks * 32 + lane) * 4;
                const uint4* wl4 = (const uint4*)(sm + XW_LO) + (ks * 32 + lane) * 4;
#pragma unroll
                for (int q4 = 0; q4 < 4; q4++) {
                    uint4 bh = wh4[q4];
                    uint4 bl = wl4[q4];
                    mma_bf16(acc[2 * q4], ah, bh.x, bh.y);
                    mma_bf16(acc[2 * q4 + 1], ah, bh.z, bh.w);
                    mma_bf16(acc[2 * q4], al, bh.x, bh.y);
                    mma_bf16(acc[2 * q4 + 1], al, bh.z, bh.w);
                    mma_bf16(acc[2 * q4], ah, bl.x, bl.y);
                    mma_bf16(acc[2 * q4 + 1], ah, bl.z, bl.w);
                }
            }
            if (ch < 3) {
                char* dh = sm + XA_HI + (buf ^ 1) * 16384;
                char* dl = sm + XA_LO + (buf ^ 1) * 16384;
#pragma unroll
                for (int i = 0; i < 4; i++) {
                    int s = i * 256 + tid;
                    int row = s >> 3, sb = s & 7;
                    int off = row * 128 + sb * 16;
                    int sw = off ^ ((off >> 3) & 0x70);
                    *(uint4*)(dh + sw) = ph[i];
                    *(uint4*)(dl + sw) = pl[i];
                }
            }
            __syncthreads();
        }

        int r0 = m0 + w * 16 + grp;
        int r1 = r0 + 8;
        size_t ob0 = ((size_t)(r0 & 255) * BB + (r0 >> 8)) * GG;
        size_t ob1 = ((size_t)(r1 & 255) * BB + (r1 >> 8)) * GG;
#pragma unroll
        for (int nt = 0; nt < 8; nt++) {
            int g = n0 + nt * 8 + tg * 2;
            float2 v0 = make_float2(acc[nt][0] + bias0[nt], acc[nt][1] + bias1[nt]);
            float2 v1 = make_float2(acc[nt][2] + bias0[nt], acc[nt][3] + bias1[nt]);
            *(float2*)&g_xproj[ob0 + g] = v0;
            *(float2*)&g_xproj[ob1 + g] = v1;
        }
    }
}

// ---------------------------------------------------------------------------
// Persistent LSTM recurrence: 128 CTAs x 512 thr, mma.sync bf16 3-term split.
// 16 warps = 4 mt x 2 nh x 2 kh. Each k-half group (8 warps, 256 thr) runs
// an independent cp.async double-buffered pipeline over its 512 k (8 x k64
// chunks) with named barriers; partial accumulators reduced via two SMEM
// gate-exchange regions in the epilogue.
// ---------------------------------------------------------------------------
__global__ __launch_bounds__(512, 1) void lstm_kernel(const float* __restrict__ Whh) {
    extern __shared__ char sm[];
    const int tid = threadIdx.x;
    const int lane = tid & 31;
    const int w = tid >> 5;           // 0..15
    const int wg = w & 7;             // warp within group
    const int mt = wg & 3, nh = wg >> 2;
    const int kh = w >> 3;            // k-half 0/1
    const int gtid = tid & 255;       // thread within group
    const int barid = 1 + kh;
    const int hc0 = blockIdx.x * 8;
    const uint32_t smb = smem_u32(sm);

    // ---- one-time: W fragment fill (hi/lo split, fragment-direct layout) ----
    for (int idx = tid; idx < 16384; idx += 512) {
        int r = idx & 3, ln = (idx >> 2) & 31, ks = (idx >> 7) & 63, nhh = idx >> 13;
        int nt = r >> 1;
        int kk = (r & 1) * 8 + (ln & 3) * 2;
        int nl = nhh * 16 + nt * 8 + (ln >> 2);
        int k = ks * 16 + kk;
        int gr = (nl >> 3) * 1024 + hc0 + (nl & 7);
        float w0 = Whh[gr * 1024 + k];
        float w1 = Whh[gr * 1024 + k + 1];
        __nv_bfloat16 h0 = __float2bfloat16(w0), h1 = __float2bfloat16(w1);
        __nv_bfloat16 l0 = __float2bfloat16(w0 - __bfloat162float(h0));
        __nv_bfloat16 l1 = __float2bfloat16(w1 - __bfloat162float(h1));
        ((uint32_t*)(sm + WF_HI))[idx] = pack2(h0, h1);
        ((uint32_t*)(sm + WF_LO))[idx] = pack2(l0, l1);
    }
    __syncthreads();

    // staging constants: each group thread stages 2 adjacent 16B segs per half
    const int srow = gtid >> 2;                 // batch row 0..63
    const int sseg = (gtid & 3) * 2;            // seg pair within 128B row
    int so0 = srow * 128 + sseg * 16;
    int so1 = so0 + 16;
    const int sw0 = so0 ^ ((so0 >> 3) & 0x70);
    const int sw1 = so1 ^ ((so1 >> 3) & 0x70);
    const int grow = srow * 128 + kh * 64 + sseg;   // uint4 idx; + ch*8 per chunk

    // A ldmatrix per-lane constants
    const int arow = mt * 16 + (lane & 15);
    const int acol = (lane >> 4) * 16;

    // A buffer bases for this group
    const uint32_t abase_h = smb + A_HI + kh * 16384;
    const uint32_t abase_l = smb + A_LO + kh * 16384;

    // epilogue ownership: 1 state per thread
    const int eb = tid & 63, ej = tid >> 6;     // ej 0..7
    float cst = 0.f;

    for (int t = 0; t < TT; t++) {
        const uint4* ghi = (const uint4*)g_hhi[t & 1];
        const uint4* glo = (const uint4*)g_hlo[t & 1];
        const float* xg = g_xproj + (size_t)t * BB * GG;
        const unsigned tgt = 16u * (unsigned)t;

        // prefetch this thread's xproj values (4 gates x 1 state)
        float xp[4];
        {
            const float* xb = xg + (size_t)eb * GG + hc0 + ej;
#pragma unroll
            for (int q = 0; q < 4; q++) xp[q] = xb[q * HH];
        }

        float acc[2][4];
#pragma unroll
        for (int z = 0; z < 2; z++)
#pragma unroll
            for (int r = 0; r < 4; r++) acc[z][r] = 0.f;

        // prologue: chunk 0 of this k-half -> buf 0
        if (t) {
            if (lane == 0) poll_ge(&g_cnt[(kh * 8) >> 1], tgt);
            __syncwarp();
        }
        cp16(abase_h + sw0, ghi + grow);
        cp16(abase_h + sw1, ghi + grow + 1);
        cp16(abase_l + sw0, glo + grow);
        cp16(abase_l + sw1, glo + grow + 1);
        CP_COMMIT();

        for (int ch = 0; ch < 8; ch++) {
            const int buf = ch & 1;
            if (ch < 7) {
                if (t) {
                    if (lane == 0) poll_ge(&g_cnt[(kh * 8 + ch + 1) >> 1], tgt);
                    __syncwarp();
                }
                const uint32_t dsth = abase_h + (buf ^ 1) * 8192;
                const uint32_t dstl = abase_l + (buf ^ 1) * 8192;
                cp16(dsth + sw0, ghi + grow + (ch + 1) * 8);
                cp16(dsth + sw1, ghi + grow + (ch + 1) * 8 + 1);
                cp16(dstl + sw0, glo + grow + (ch + 1) * 8);
                cp16(dstl + sw1, glo + grow + (ch + 1) * 8 + 1);
                CP_COMMIT();
                CP_WAIT(1);
            } else {
                CP_WAIT(0);
            }
            GBAR(barid);

            const uint32_t abh = abase_h + buf * 8192;
            const uint32_t abl = abase_l + buf * 8192;
            const uint4* wfh = (const uint4*)(sm + WF_HI) + ((nh * 64 + kh * 32 + ch * 4) * 32 + lane);
            const uint4* wfl = (const uint4*)(sm + WF_LO) + ((nh * 64 + kh * 32 + ch * 4) * 32 + lane);
#pragma unroll
            for (int kl = 0; kl < 4; kl++) {
                int off = arow * 128 + kl * 32 + acol;
                int sw = off ^ ((off >> 3) & 0x70);
                uint32_t ah[4], al[4];
                ldm_x4(ah, abh + sw);
                ldm_x4(al, abl + sw);
                uint4 bh = wfh[kl * 32];
                uint4 bl = wfl[kl * 32];
                mma_bf16(acc[0], ah, bh.x, bh.y);
                mma_bf16(acc[1], ah, bh.z, bh.w);
                mma_bf16(acc[0], al, bh.x, bh.y);
                mma_bf16(acc[1], al, bh.z, bh.w);
                mma_bf16(acc[0], ah, bl.x, bl.y);
                mma_bf16(acc[1], ah, bl.z, bl.w);
            }
            GBAR(barid);
        }

        // epilogue: write partial sums to this k-half's gate-exchange region
        {
            float* sg = (float*)(sm + SG0 + kh * 9216);
            int grp = lane >> 2, tg = lane & 3;
#pragma unroll
            for (int nt = 0; nt < 2; nt++) {
                int col = nh * 16 + nt * 8 + tg * 2;
                int row = mt * 16 + grp;
                sg[col * 72 + row] = acc[nt][0];
                sg[(col + 1) * 72 + row] = acc[nt][1];
                sg[col * 72 + row + 8] = acc[nt][2];
                sg[(col + 1) * 72 + row + 8] = acc[nt][3];
            }
        }
        __syncthreads();

        // pointwise update (fast math): 512 states, 1 per thread
        {
            const float* sg1 = (const float*)(sm + SG0);
            const float* sg2 = (const float*)(sm + SG0 + 9216);
            float iv = sg1[(0 + ej) * 72 + eb] + sg2[(0 + ej) * 72 + eb] + xp[0];
            float fv = sg1[(8 + ej) * 72 + eb] + sg2[(8 + ej) * 72 + eb] + xp[1];
            float gv = sg1[(16 + ej) * 72 + eb] + sg2[(16 + ej) * 72 + eb] + xp[2];
            float ov = sg1[(24 + ej) * 72 + eb] + sg2[(24 + ej) * 72 + eb] + xp[3];
            float cn = fsigmoid(fv) * cst + fsigmoid(iv) * ftanh(gv);
            cst = cn;
            float hn = fsigmoid(ov) * ftanh(cn);
            __nv_bfloat16 hbb = __float2bfloat16(hn);
            g_hhi[(t + 1) & 1][eb * HH + hc0 + ej] = hbb;
            g_hlo[(t + 1) & 1][eb * HH + hc0 + ej] = __float2bfloat16(hn - __bfloat162float(hbb));
        }
        __syncthreads();
        if (tid == 0) {
            __threadfence();                            // order h stores (gpu scope)
            atomicAdd(&g_cnt[blockIdx.x >> 4], 1u);     // signal this group's step done
        }
    }
}

// ---------------------------------------------------------------------------
// logits = h_last @ fc_w^T + fc_b; out = log_softmax.  grid=64, block=256.
// ---------------------------------------------------------------------------
__global__ __launch_bounds__(256) void fc_kernel(const float* __restrict__ fcw,
                                                 const float* __restrict__ fcb,
                                                 float* __restrict__ out) {
    __shared__ float sh[HH];
    __shared__ float sl[64];
    __shared__ float s_red[2];
    int b = blockIdx.x;
    int tid = threadIdx.x;
    int w = tid >> 5, lane = tid & 31;

    {
        uint2 vh = ((const uint2*)(g_hhi[0] + b * HH))[tid];
        uint2 vl = ((const uint2*)(g_hlo[0] + b * HH))[tid];
        float2 h0 = unpack2(vh.x), h1 = unpack2(vh.y);
        float2 l0 = unpack2(vl.x), l1 = unpack2(vl.y);
        float4 f = make_float4(h0.x + l0.x, h0.y + l0.y, h1.x + l1.x, h1.y + l1.y);
        ((float4*)sh)[tid] = f;
    }
    __syncthreads();

#pragma unroll
    for (int cc = 0; cc < 8; cc++) {
        int c = w * 8 + cc;
        float s = 0.f;
        if (c < CC) {
            const float* wr = fcw + c * HH;
#pragma unroll 8
            for (int i = 0; i < 32; i++) {
                int k = i * 32 + lane;
                s += sh[k] * wr[k];
            }
        }
#pragma unroll
        for (int off = 16; off > 0; off >>= 1) s += __shfl_xor_sync(0xFFFFFFFF, s, off);
        if (lane == 0) sl[c] = (c < CC) ? s + fcb[c] : -1e30f;
    }
    __syncthreads();

    if (w == 0) {
        float v0 = sl[lane], v1 = sl[lane + 32];
        float m = fmaxf(v0, v1);
#pragma unroll
        for (int off = 16; off > 0; off >>= 1) m = fmaxf(m, __shfl_xor_sync(0xFFFFFFFF, m, off));
        float e = expf(v0 - m) + expf(v1 - m);
#pragma unroll
        for (int off = 16; off > 0; off >>= 1) e += __shfl_xor_sync(0xFFFFFFFF, e, off);
        if (lane == 0) { s_red[0] = m; s_red[1] = logf(e); }
    }
    __syncthreads();
    if (tid < CC) out[b * CC + tid] = sl[tid] - s_red[0] - s_red[1];
}

// ---------------------------------------------------------------------------
extern "C" void kernel_launch(void* const* d_in, const int* in_sizes, int n_in,
                              void* d_out, int out_size) {
    const float* inp = (const float*)d_in[0];   // [B,T,I]
    const float* Wih = (const float*)d_in[1];   // [4H,I]
    const float* Whh = (const float*)d_in[2];   // [4H,H]
    const float* bih = (const float*)d_in[3];   // [4H]
    const float* bhh = (const float*)d_in[4];   // [4H]
    const float* fcw = (const float*)d_in[5];   // [C,H]
    const float* fcb = (const float*)d_in[6];   // [C]
    float* out = (float*)d_out;                 // [B,C]

    cudaFuncSetAttribute(lstm_kernel, cudaFuncAttributeMaxDynamicSharedMemorySize, SMEM_DYN);
    cudaFuncSetAttribute(xproj_mma_kernel, cudaFuncAttributeMaxDynamicSharedMemorySize, SMEM_X);

    zero_kernel<<<512, 256>>>();
    conv_kernel<<<1024, 256>>>(inp, Wih);

    dim3 gx(64, 16);
    xproj_mma_kernel<<<gx, 256, SMEM_X>>>(bih, bhh);

    lstm_kernel<<<NCTA, 512, SMEM_DYN>>>(Whh);

    fc_kernel<<<BB, 64 * 4>>>(fcw, fcb, out);
}